// round 10
// baseline (speedup 1.0000x reference)
#include <cuda_runtime.h>
#include <cuda_fp16.h>
#include <math.h>
#include <cstdint>

#define B 4
#define H 16
#define S 2048
#define DM 1024
#define DH 64
#define SCALE 0.125f
#define NTOK (B*S)   // 8192

// ---------------------------------------------------------------------------
// Scratch (device globals: no allocations allowed)
// A-side operands: hi only. B-side operands: hi+lo (fp16 2-term scheme).
// ---------------------------------------------------------------------------
__device__ __half gx[(size_t)NTOK*DM];
__device__ __half gw_hi[(size_t)3*H*DH*DM], gw_lo[(size_t)3*H*DH*DM];
__device__ __half gwo_hi[(size_t)DM*DM], gwo_lo[(size_t)DM*DM];
__device__ __half gh[(size_t)NTOK*DM];

__device__ __half gq[(size_t)B*H*S*DH];
__device__ __half gk_hi[(size_t)B*H*S*DH], gk_lo[(size_t)B*H*S*DH];
__device__ __half gvt_hi[(size_t)B*H*DH*S], gvt_lo[(size_t)B*H*DH*S];

// ---------------------------------------------------------------------------
// PTX helpers (sm_80-level, valid under compute_103)
// ---------------------------------------------------------------------------
__device__ __forceinline__ uint32_t smem_u32(const void* p) {
    uint32_t a;
    asm("{ .reg .u64 t; cvta.to.shared.u64 t, %1; cvt.u32.u64 %0, t; }" : "=r"(a) : "l"(p));
    return a;
}

#define LDSM_X4(r0, r1, r2, r3, addr) \
    asm volatile("ldmatrix.sync.aligned.m8n8.x4.shared.b16 {%0,%1,%2,%3}, [%4];" \
                 : "=r"(r0), "=r"(r1), "=r"(r2), "=r"(r3) : "r"(addr))

__device__ __forceinline__ void mma_fp16(float* c, const uint32_t* a, const uint32_t* b) {
    asm volatile("mma.sync.aligned.m16n8k16.row.col.f32.f16.f16.f32 "
                 "{%0,%1,%2,%3}, {%4,%5,%6,%7}, {%8,%9}, {%0,%1,%2,%3};"
                 : "+f"(c[0]), "+f"(c[1]), "+f"(c[2]), "+f"(c[3])
                 : "r"(a[0]), "r"(a[1]), "r"(a[2]), "r"(a[3]), "r"(b[0]), "r"(b[1]));
}

#define CP_ASYNC16(dst_u32, src_ptr) \
    asm volatile("cp.async.ca.shared.global [%0], [%1], 16;" \
                 :: "r"(dst_u32), "l"(src_ptr) : "memory")
#define CP_COMMIT() asm volatile("cp.async.commit_group;" ::: "memory")
#define CP_WAIT(n)  asm volatile("cp.async.wait_group %0;" :: "n"(n) : "memory")

__device__ __forceinline__ void split2h(float a, __half& h, __half& l) {
    h = __float2half_rn(a);
    l = __float2half_rn(a - __half2float(h));
}

// ---------------------------------------------------------------------------
// Fused prep (validated R8): x->fp16, W q/k/v + Wo transpose+split. 1 launch.
// ---------------------------------------------------------------------------
__global__ __launch_bounds__(256) void prep_kernel(
    const float* __restrict__ x,
    const float* __restrict__ Wq, const float* __restrict__ Wk, const float* __restrict__ Wv,
    const float* __restrict__ Wo)
{
    const int bid = blockIdx.x;
    const int tid = threadIdx.x;

    if (bid < 2048) {
        __half2* dp = (__half2*)gx;
        #pragma unroll
        for (int j = 0; j < 4; j++) {
            int i = bid * 1024 + j * 256 + tid;
            float4 v = ((const float4*)x)[i];
            dp[2*i]   = __floats2half2_rn(v.x, v.y);
            dp[2*i+1] = __floats2half2_rn(v.z, v.w);
        }
        return;
    }

    __shared__ float tile[32][33];
    const int t = bid - 2048;
    const float* src;
    __half *dst_hi, *dst_lo;
    int d0, e0, in_stride, out_stride;
    size_t in_base, out_base;

    if (t < 3072) {
        const int which = t >> 10;
        const int r = t & 1023;
        const int h = r >> 6;
        const int tl = r & 63;
        const int tk = tl >> 1, te = tl & 1;
        src = (which == 0) ? Wq : (which == 1) ? Wk : Wv;
        d0 = tk * 32; e0 = te * 32;
        in_stride = DH; out_stride = DM;
        in_base  = (size_t)h * DM * DH;
        out_base = ((size_t)(which * H + h) * DH) * DM;
        dst_hi = gw_hi; dst_lo = gw_lo;
    } else {
        const int t2 = t - 3072;
        d0 = (t2 >> 5) * 32; e0 = (t2 & 31) * 32;
        src = Wo; in_stride = DM; out_stride = DM;
        in_base = 0; out_base = 0;
        dst_hi = gwo_hi; dst_lo = gwo_lo;
    }

    const int tx = tid & 31, ty = tid >> 5;
    #pragma unroll
    for (int p = 0; p < 4; p++) {
        int row = ty + p * 8;
        tile[row][tx] = src[in_base + (size_t)(d0 + row) * in_stride + e0 + tx];
    }
    __syncthreads();
    #pragma unroll
    for (int p = 0; p < 4; p++) {
        int erow = ty + p * 8;
        float v = tile[tx][erow];
        __half h, l; split2h(v, h, l);
        size_t oi = out_base + (size_t)(e0 + erow) * out_stride + d0 + tx;
        dst_hi[oi] = h; dst_lo[oi] = l;
    }
}

// ---------------------------------------------------------------------------
// GEMM core v4: 256(M) x 128(N), 512 threads, 3-stage cp.async pipeline,
// SINGLE __syncthreads per stage (wait -> sync -> prefetch(s+2) -> compute).
// ---------------------------------------------------------------------------
#define PA 72
#define G_A 0
#define G_BHI (256 * PA)
#define G_BLO (256 * PA + 128 * PA)
#define G_STAGE (512 * PA)                // halves per stage
#define GSM_BYTES (3 * G_STAGE * 2)       // 221184 B

__device__ __forceinline__ void g_prefetch(
    uint32_t sb, int buf,
    const __half* a, size_t arow0,
    const __half* b_hi, const __half* b_lo, size_t brow0,
    int k0, int tid)
{
    uint32_t st = sb + (uint32_t)buf * G_STAGE * 2;
    #pragma unroll
    for (int it = 0; it < 4; it++) {
        int c = it * 512 + tid;
        int row = c >> 3, c8 = c & 7;
        uint32_t so = (uint32_t)(row * PA + c8 * 8) * 2;
        CP_ASYNC16(st + G_A * 2 + so, a + (arow0 + row) * (size_t)DM + k0 + c8 * 8);
    }
    #pragma unroll
    for (int it = 0; it < 2; it++) {
        int c = it * 512 + tid;
        int row = c >> 3, c8 = c & 7;
        uint32_t so = (uint32_t)(row * PA + c8 * 8) * 2;
        size_t gb = (brow0 + row) * (size_t)DM + k0 + c8 * 8;
        CP_ASYNC16(st + G_BHI * 2 + so, b_hi + gb);
        CP_ASYNC16(st + G_BLO * 2 + so, b_lo + gb);
    }
}

__device__ __forceinline__ void gemm_tile_mma(
    const __half* __restrict__ a, size_t arow0,
    const __half* __restrict__ b_hi, const __half* __restrict__ b_lo, size_t brow0,
    float acc[4][4][4])
{
    extern __shared__ __half sm[];
    const int tid = threadIdx.x;
    const int wid = tid >> 5, lane = tid & 31;
    const int mg = (wid & 3) * 64;
    const int ng = (wid >> 2) * 32;

    #pragma unroll
    for (int m = 0; m < 4; m++)
        #pragma unroll
        for (int n = 0; n < 4; n++)
            #pragma unroll
            for (int v = 0; v < 4; v++) acc[m][n][v] = 0.f;

    const uint32_t sb = smem_u32(sm);
    const int a_row_l = (lane & 15);
    const int a_col_l = ((lane >> 4) << 3);
    const int b_row_l = ((lane >> 4) << 3) + (lane & 7);
    const int b_col_l = (((lane >> 3) & 1) << 3);

    g_prefetch(sb, 0, a, arow0, b_hi, b_lo, brow0, 0, tid);
    CP_COMMIT();
    g_prefetch(sb, 1, a, arow0, b_hi, b_lo, brow0, 64, tid);
    CP_COMMIT();

    int bufc = 0, bufp = 2;
    for (int s = 0; s < 16; s++) {
        if (s < 15) { CP_WAIT(1); } else { CP_WAIT(0); }
        __syncthreads();            // all warps done with stage s-1 + stage s visible
        if (s + 2 < 16) {
            g_prefetch(sb, bufp, a, arow0, b_hi, b_lo, brow0, (s + 2) * 64, tid);
            CP_COMMIT();
        }

        const uint32_t st = sb + (uint32_t)bufc * G_STAGE * 2;
        #pragma unroll
        for (int ks = 0; ks < 4; ks++) {
            uint32_t ar[4][4];
            #pragma unroll
            for (int m = 0; m < 4; m++) {
                uint32_t off = (uint32_t)((mg + m * 16 + a_row_l) * PA + ks * 16 + a_col_l) * 2;
                LDSM_X4(ar[m][0], ar[m][1], ar[m][2], ar[m][3], st + G_A * 2 + off);
            }
            #pragma unroll
            for (int p = 0; p < 2; p++) {
                uint32_t off = (uint32_t)((ng + p * 16 + b_row_l) * PA + ks * 16 + b_col_l) * 2;
                uint32_t bh4[4], bl4[4];
                LDSM_X4(bh4[0], bh4[1], bh4[2], bh4[3], st + G_BHI * 2 + off);
                LDSM_X4(bl4[0], bl4[1], bl4[2], bl4[3], st + G_BLO * 2 + off);
                #pragma unroll
                for (int m = 0; m < 4; m++) {
                    mma_fp16(acc[m][2*p],   ar[m], bh4);
                    mma_fp16(acc[m][2*p],   ar[m], bl4);
                    mma_fp16(acc[m][2*p+1], ar[m], bh4 + 2);
                    mma_fp16(acc[m][2*p+1], ar[m], bl4 + 2);
                }
            }
        }
        bufc = (bufc == 2) ? 0 : bufc + 1;
        bufp = (bufp == 2) ? 0 : bufp + 1;
    }
}

// ---------------------------------------------------------------------------
// QKV GEMM: grid (32 mtiles of 256, 24 ntiles of 128).
// ---------------------------------------------------------------------------
__global__ __launch_bounds__(512) void gemm_qkv_tc(
    const float* __restrict__ bq, const float* __restrict__ bk, const float* __restrict__ bv)
{
    const int mt = blockIdx.x, nt = blockIdx.y;
    const size_t arow0 = (size_t)mt * 256;
    const size_t brow0 = (size_t)nt * 128;

    float acc[4][4][4];
    gemm_tile_mma(gx, arow0, gw_hi, gw_lo, brow0, acc);

    const int tid = threadIdx.x, wid = tid >> 5, lane = tid & 31;
    const int mg = (wid & 3) * 64;
    const int gcol0 = nt * 128 + (wid >> 2) * 32;
    const int which = gcol0 >> 10;
    const int h = (gcol0 & 1023) >> 6;
    const float* bias = (which == 0) ? bq : (which == 1) ? bk : bv;

    #pragma unroll
    for (int m = 0; m < 4; m++) {
        #pragma unroll
        for (int n4 = 0; n4 < 4; n4++) {
            #pragma unroll
            for (int half_ = 0; half_ < 2; half_++) {
                int r = mg + m * 16 + (lane >> 2) + half_ * 8;
                int e = (gcol0 & 63) + n4 * 8 + (lane & 3) * 2;
                size_t mrow = arow0 + r;
                int b = (int)(mrow / S), sidx = (int)(mrow % S);
                int bhidx = b * H + h;
                float v0 = acc[m][n4][half_ * 2 + 0] + bias[h * DH + e];
                float v1 = acc[m][n4][half_ * 2 + 1] + bias[h * DH + e + 1];
                if (which == 0) {
                    v0 *= SCALE; v1 *= SCALE;
                    size_t base = ((size_t)bhidx * S + sidx) * DH + e;
                    *(__half2*)&gq[base] = __floats2half2_rn(v0, v1);
                } else if (which == 1) {
                    __half h0, l0, h1, l1;
                    split2h(v0, h0, l0); split2h(v1, h1, l1);
                    size_t base = ((size_t)bhidx * S + sidx) * DH + e;
                    __half2 th; th.x = h0; th.y = h1;
                    __half2 tl; tl.x = l0; tl.y = l1;
                    *(__half2*)&gk_hi[base] = th;
                    *(__half2*)&gk_lo[base] = tl;
                } else {
                    __half h0, l0, h1, l1;
                    split2h(v0, h0, l0); split2h(v1, h1, l1);
                    size_t base = ((size_t)bhidx * DH + e) * S + sidx;
                    gvt_hi[base] = h0;     gvt_lo[base] = l0;
                    gvt_hi[base + S] = h1; gvt_lo[base + S] = l1;
                }
            }
        }
    }
}

// ---------------------------------------------------------------------------
// Output GEMM: grid (32 mtiles of 256, 8 ntiles of 128).
// ---------------------------------------------------------------------------
__global__ __launch_bounds__(512) void gemm_out_tc(const float* __restrict__ bo,
                                                   float* __restrict__ out)
{
    const int mt = blockIdx.x, nt = blockIdx.y;
    const size_t arow0 = (size_t)mt * 256;

    float acc[4][4][4];
    gemm_tile_mma(gh, arow0, gwo_hi, gwo_lo, (size_t)nt * 128, acc);

    const int tid = threadIdx.x, wid = tid >> 5, lane = tid & 31;
    const int mg = (wid & 3) * 64;
    const int gcol0 = nt * 128 + (wid >> 2) * 32;

    #pragma unroll
    for (int m = 0; m < 4; m++) {
        #pragma unroll
        for (int n4 = 0; n4 < 4; n4++) {
            #pragma unroll
            for (int half_ = 0; half_ < 2; half_++) {
                int r = mg + m * 16 + (lane >> 2) + half_ * 8;
                int c = gcol0 + n4 * 8 + (lane & 3) * 2;
                size_t mrow = arow0 + r;
                float2 w = {acc[m][n4][half_ * 2 + 0] + bo[c],
                            acc[m][n4][half_ * 2 + 1] + bo[c + 1]};
                *(float2*)&out[mrow * DM + c] = w;
            }
        }
    }
}

// ---------------------------------------------------------------------------
// Attention (FA2, fp16 2-term), double-buffered KV, SINGLE sync per kt-tile.
// ---------------------------------------------------------------------------
#define A_Q 0
#define A_KV0 (128 * PA)
#define A_KV_COMP (64 * PA)
#define A_KV_STAGE (4 * A_KV_COMP)
#define ATT_BYTES ((128 * PA + 2 * A_KV_STAGE) * 2)   // 92160 B

__device__ __forceinline__ void a_prefetch_kv(uint32_t sb, int buf, int bh, int kt, int tid)
{
    uint32_t st = sb + (uint32_t)(A_KV0 + buf * A_KV_STAGE) * 2;
    #pragma unroll
    for (int it = 0; it < 2; it++) {
        int c = it * 256 + tid;
        int row = c >> 3, c8 = c & 7;
        uint32_t so = (uint32_t)(row * PA + c8 * 8) * 2;
        size_t gk = ((size_t)bh * S + kt * 64 + row) * DH + c8 * 8;
        size_t gv = ((size_t)bh * DH + row) * S + kt * 64 + c8 * 8;
        CP_ASYNC16(st + 0 * A_KV_COMP * 2 + so, gk_hi + gk);
        CP_ASYNC16(st + 1 * A_KV_COMP * 2 + so, gk_lo + gk);
        CP_ASYNC16(st + 2 * A_KV_COMP * 2 + so, gvt_hi + gv);
        CP_ASYNC16(st + 3 * A_KV_COMP * 2 + so, gvt_lo + gv);
    }
}

__global__ __launch_bounds__(256) void attn_mma()
{
    extern __shared__ __half sm[];
    const int qt = blockIdx.x;
    const int bh = blockIdx.y;
    const int tid = threadIdx.x, wid = tid >> 5, lane = tid & 31;
    const int base_m = wid * 16;
    const uint32_t sb = smem_u32(sm);
    const int a_row_l = (lane & 15);
    const int a_col_l = ((lane >> 4) << 3);
    const int b_row_l = ((lane >> 4) << 3) + (lane & 7);
    const int b_col_l = (((lane >> 3) & 1) << 3);

    a_prefetch_kv(sb, 0, bh, 0, tid);
    CP_COMMIT();

    const size_t qbase = ((size_t)bh * S + qt * 128) * DH;
    #pragma unroll
    for (int it = 0; it < 4; it++) {
        int c = it * 256 + tid;
        int row = c >> 3, c8 = c & 7;
        *(uint4*)&sm[A_Q + row * PA + c8 * 8] = *(const uint4*)(gq + qbase + (size_t)row * DH + c8 * 8);
    }

    float o[8][4];
    #pragma unroll
    for (int n = 0; n < 8; n++)
        #pragma unroll
        for (int v = 0; v < 4; v++) o[n][v] = 0.f;
    float mrow[2] = {-INFINITY, -INFINITY};
    float lrow[2] = {0.f, 0.f};

    for (int kt = 0; kt < S / 64; kt++) {
        const int buf = kt & 1;
        CP_WAIT(0);
        __syncthreads();            // all warps done with buf^1 readers + buf visible
        if (kt + 1 < S / 64) {
            a_prefetch_kv(sb, buf ^ 1, bh, kt + 1, tid);
            CP_COMMIT();
        }

        const uint32_t st = sb + (uint32_t)(A_KV0 + buf * A_KV_STAGE) * 2;

        float sc[8][4];
        #pragma unroll
        for (int n = 0; n < 8; n++)
            #pragma unroll
            for (int v = 0; v < 4; v++) sc[n][v] = 0.f;

        #pragma unroll
        for (int ks = 0; ks < 4; ks++) {
            uint32_t ar[4];
            uint32_t aoff = (uint32_t)((base_m + a_row_l) * PA + ks * 16 + a_col_l) * 2;
            LDSM_X4(ar[0], ar[1], ar[2], ar[3], sb + A_Q * 2 + aoff);
            #pragma unroll
            for (int p = 0; p < 4; p++) {
                uint32_t boff = (uint32_t)((p * 16 + b_row_l) * PA + ks * 16 + b_col_l) * 2;
                uint32_t kh4[4], kl4[4];
                LDSM_X4(kh4[0], kh4[1], kh4[2], kh4[3], st + 0 * A_KV_COMP * 2 + boff);
                LDSM_X4(kl4[0], kl4[1], kl4[2], kl4[3], st + 1 * A_KV_COMP * 2 + boff);
                mma_fp16(sc[2*p],   ar, kh4);
                mma_fp16(sc[2*p],   ar, kl4);
                mma_fp16(sc[2*p+1], ar, kh4 + 2);
                mma_fp16(sc[2*p+1], ar, kl4 + 2);
            }
        }

        #pragma unroll
        for (int half_ = 0; half_ < 2; half_++) {
            const int ci = half_ * 2;
            float mx = -INFINITY;
            #pragma unroll
            for (int n = 0; n < 8; n++)
                mx = fmaxf(mx, fmaxf(sc[n][ci], sc[n][ci + 1]));
            mx = fmaxf(mx, __shfl_xor_sync(0xffffffffu, mx, 1));
            mx = fmaxf(mx, __shfl_xor_sync(0xffffffffu, mx, 2));
            float mnew = fmaxf(mrow[half_], mx);
            float f = __expf(mrow[half_] - mnew);
            mrow[half_] = mnew;
            float rs = 0.f;
            #pragma unroll
            for (int n = 0; n < 8; n++) {
                sc[n][ci]     = __expf(sc[n][ci]     - mnew);
                sc[n][ci + 1] = __expf(sc[n][ci + 1] - mnew);
                rs += sc[n][ci] + sc[n][ci + 1];
            }
            rs += __shfl_xor_sync(0xffffffffu, rs, 1);
            rs += __shfl_xor_sync(0xffffffffu, rs, 2);
            lrow[half_] = lrow[half_] * f + rs;
            #pragma unroll
            for (int n = 0; n < 8; n++) {
                o[n][ci] *= f;
                o[n][ci + 1] *= f;
            }
        }

        uint32_t pa[4][4];
        #pragma unroll
        for (int ks = 0; ks < 4; ks++) {
            #pragma unroll
            for (int q = 0; q < 4; q++) {
                int n = 2 * ks + (q >> 1);
                int pr = (q & 1) * 2;
                __half2 t = __floats2half2_rn(sc[n][pr], sc[n][pr + 1]);
                pa[ks][q] = *(uint32_t*)&t;
            }
        }

        #pragma unroll
        for (int ks = 0; ks < 4; ks++) {
            #pragma unroll
            for (int p = 0; p < 4; p++) {
                uint32_t boff = (uint32_t)((p * 16 + b_row_l) * PA + ks * 16 + b_col_l) * 2;
                uint32_t vh4[4], vl4[4];
                LDSM_X4(vh4[0], vh4[1], vh4[2], vh4[3], st + 2 * A_KV_COMP * 2 + boff);
                LDSM_X4(vl4[0], vl4[1], vl4[2], vl4[3], st + 3 * A_KV_COMP * 2 + boff);
                mma_fp16(o[2*p],   pa[ks], vh4);
                mma_fp16(o[2*p],   pa[ks], vl4);
                mma_fp16(o[2*p+1], pa[ks], vh4 + 2);
                mma_fp16(o[2*p+1], pa[ks], vl4 + 2);
            }
        }
        // no trailing sync: next iteration's top sync covers the WAR hazard
    }

    const float inv0 = 1.f / lrow[0];
    const float inv1 = 1.f / lrow[1];
    const int b = bh >> 4, h = bh & 15;
    const int s0 = qt * 128 + base_m + (lane >> 2);
    const size_t tok0 = (size_t)b * S + s0;
    const size_t tok1 = tok0 + 8;
    #pragma unroll
    for (int n = 0; n < 8; n++) {
        int col = h * DH + n * 8 + (lane & 3) * 2;
        *(__half2*)&gh[tok0 * DM + col] = __floats2half2_rn(o[n][0] * inv0, o[n][1] * inv0);
        *(__half2*)&gh[tok1 * DM + col] = __floats2half2_rn(o[n][2] * inv1, o[n][3] * inv1);
    }
}

// ---------------------------------------------------------------------------
extern "C" void kernel_launch(void* const* d_in, const int* in_sizes, int n_in,
                              void* d_out, int out_size)
{
    const float* x  = (const float*)d_in[0];
    const float* Wq = (const float*)d_in[1];
    const float* bq = (const float*)d_in[2];
    const float* Wk = (const float*)d_in[3];
    const float* bk = (const float*)d_in[4];
    const float* Wv = (const float*)d_in[5];
    const float* bv = (const float*)d_in[6];
    const float* Wo = (const float*)d_in[7];
    const float* bo = (const float*)d_in[8];
    float* out = (float*)d_out;

    static bool init = false;
    if (!init) {
        cudaFuncSetAttribute(gemm_qkv_tc, cudaFuncAttributeMaxDynamicSharedMemorySize, GSM_BYTES);
        cudaFuncSetAttribute(gemm_out_tc, cudaFuncAttributeMaxDynamicSharedMemorySize, GSM_BYTES);
        cudaFuncSetAttribute(attn_mma,    cudaFuncAttributeMaxDynamicSharedMemorySize, ATT_BYTES);
        init = true;
    }

    // 1. fused prep
    prep_kernel<<<6144, 256>>>(x, Wq, Wk, Wv, Wo);

    // 2. QKV projection (fp16 2-term HMMA, 3-stage pipeline)
    gemm_qkv_tc<<<dim3(32, 24), 512, GSM_BYTES>>>(bq, bk, bv);

    // 3. attention (fp16 2-term HMMA, single-sync pipeline)
    attn_mma<<<dim3(16, 64), 256, ATT_BYTES>>>();

    // 4. output projection
    gemm_out_tc<<<dim3(32, 8), 512, GSM_BYTES>>>(bo, out);
}

// round 11
// speedup vs baseline: 1.5873x; 1.5873x over previous
#include <cuda_runtime.h>
#include <cuda_fp16.h>
#include <math.h>
#include <cstdint>

#define B 4
#define H 16
#define S 2048
#define DM 1024
#define DH 64
#define SCALE 0.125f
#define NTOK (B*S)   // 8192

// ---------------------------------------------------------------------------
// Scratch (device globals: no allocations allowed)
// A-side operands: hi only. B-side operands: hi+lo (fp16 2-term scheme).
// ---------------------------------------------------------------------------
__device__ __half gx[(size_t)NTOK*DM];
__device__ __half gw_hi[(size_t)3*H*DH*DM], gw_lo[(size_t)3*H*DH*DM];
__device__ __half gwo_hi[(size_t)DM*DM], gwo_lo[(size_t)DM*DM];
__device__ __half gh[(size_t)NTOK*DM];

__device__ __half gq[(size_t)B*H*S*DH];
__device__ __half gk_hi[(size_t)B*H*S*DH], gk_lo[(size_t)B*H*S*DH];
__device__ __half gvt_hi[(size_t)B*H*DH*S], gvt_lo[(size_t)B*H*DH*S];

// ---------------------------------------------------------------------------
// PTX helpers (sm_80-level, valid under compute_103)
// ---------------------------------------------------------------------------
__device__ __forceinline__ uint32_t smem_u32(const void* p) {
    uint32_t a;
    asm("{ .reg .u64 t; cvta.to.shared.u64 t, %1; cvt.u32.u64 %0, t; }" : "=r"(a) : "l"(p));
    return a;
}

#define LDSM_X4(r0, r1, r2, r3, addr) \
    asm volatile("ldmatrix.sync.aligned.m8n8.x4.shared.b16 {%0,%1,%2,%3}, [%4];" \
                 : "=r"(r0), "=r"(r1), "=r"(r2), "=r"(r3) : "r"(addr))

__device__ __forceinline__ void mma_fp16(float* c, const uint32_t* a, const uint32_t* b) {
    asm volatile("mma.sync.aligned.m16n8k16.row.col.f32.f16.f16.f32 "
                 "{%0,%1,%2,%3}, {%4,%5,%6,%7}, {%8,%9}, {%0,%1,%2,%3};"
                 : "+f"(c[0]), "+f"(c[1]), "+f"(c[2]), "+f"(c[3])
                 : "r"(a[0]), "r"(a[1]), "r"(a[2]), "r"(a[3]), "r"(b[0]), "r"(b[1]));
}

#define CP_ASYNC16(dst_u32, src_ptr) \
    asm volatile("cp.async.ca.shared.global [%0], [%1], 16;" \
                 :: "r"(dst_u32), "l"(src_ptr) : "memory")
#define CP_COMMIT() asm volatile("cp.async.commit_group;" ::: "memory")
#define CP_WAIT(n)  asm volatile("cp.async.wait_group %0;" :: "n"(n) : "memory")

__device__ __forceinline__ void split2h(float a, __half& h, __half& l) {
    h = __float2half_rn(a);
    l = __float2half_rn(a - __half2float(h));
}

// ---------------------------------------------------------------------------
// Fused prep (validated R8)
// ---------------------------------------------------------------------------
__global__ __launch_bounds__(256) void prep_kernel(
    const float* __restrict__ x,
    const float* __restrict__ Wq, const float* __restrict__ Wk, const float* __restrict__ Wv,
    const float* __restrict__ Wo)
{
    const int bid = blockIdx.x;
    const int tid = threadIdx.x;

    if (bid < 2048) {
        __half2* dp = (__half2*)gx;
        #pragma unroll
        for (int j = 0; j < 4; j++) {
            int i = bid * 1024 + j * 256 + tid;
            float4 v = ((const float4*)x)[i];
            dp[2*i]   = __floats2half2_rn(v.x, v.y);
            dp[2*i+1] = __floats2half2_rn(v.z, v.w);
        }
        return;
    }

    __shared__ float tile[32][33];
    const int t = bid - 2048;
    const float* src;
    __half *dst_hi, *dst_lo;
    int d0, e0, in_stride, out_stride;
    size_t in_base, out_base;

    if (t < 3072) {
        const int which = t >> 10;
        const int r = t & 1023;
        const int h = r >> 6;
        const int tl = r & 63;
        const int tk = tl >> 1, te = tl & 1;
        src = (which == 0) ? Wq : (which == 1) ? Wk : Wv;
        d0 = tk * 32; e0 = te * 32;
        in_stride = DH; out_stride = DM;
        in_base  = (size_t)h * DM * DH;
        out_base = ((size_t)(which * H + h) * DH) * DM;
        dst_hi = gw_hi; dst_lo = gw_lo;
    } else {
        const int t2 = t - 3072;
        d0 = (t2 >> 5) * 32; e0 = (t2 & 31) * 32;
        src = Wo; in_stride = DM; out_stride = DM;
        in_base = 0; out_base = 0;
        dst_hi = gwo_hi; dst_lo = gwo_lo;
    }

    const int tx = tid & 31, ty = tid >> 5;
    #pragma unroll
    for (int p = 0; p < 4; p++) {
        int row = ty + p * 8;
        tile[row][tx] = src[in_base + (size_t)(d0 + row) * in_stride + e0 + tx];
    }
    __syncthreads();
    #pragma unroll
    for (int p = 0; p < 4; p++) {
        int erow = ty + p * 8;
        float v = tile[tx][erow];
        __half h, l; split2h(v, h, l);
        size_t oi = out_base + (size_t)(e0 + erow) * out_stride + d0 + tx;
        dst_hi[oi] = h; dst_lo[oi] = l;
    }
}

// ---------------------------------------------------------------------------
// GEMM core (R8 structure: 2-stage, 147KB) with SINGLE sync per stage:
// wait(0) -> sync -> prefetch(s+1 into buf^1) -> compute(buf).
// ---------------------------------------------------------------------------
#define PA 72
#define G_A 0
#define G_BHI (256 * PA)
#define G_BLO (256 * PA + 128 * PA)
#define G_STAGE (512 * PA)                // halves per stage
#define GSM_BYTES (2 * G_STAGE * 2)       // 147456 B

__device__ __forceinline__ void g_prefetch(
    uint32_t sb, int buf,
    const __half* a, size_t arow0,
    const __half* b_hi, const __half* b_lo, size_t brow0,
    int k0, int tid)
{
    uint32_t st = sb + (uint32_t)buf * G_STAGE * 2;
    #pragma unroll
    for (int it = 0; it < 4; it++) {
        int c = it * 512 + tid;
        int row = c >> 3, c8 = c & 7;
        uint32_t so = (uint32_t)(row * PA + c8 * 8) * 2;
        CP_ASYNC16(st + G_A * 2 + so, a + (arow0 + row) * (size_t)DM + k0 + c8 * 8);
    }
    #pragma unroll
    for (int it = 0; it < 2; it++) {
        int c = it * 512 + tid;
        int row = c >> 3, c8 = c & 7;
        uint32_t so = (uint32_t)(row * PA + c8 * 8) * 2;
        size_t gb = (brow0 + row) * (size_t)DM + k0 + c8 * 8;
        CP_ASYNC16(st + G_BHI * 2 + so, b_hi + gb);
        CP_ASYNC16(st + G_BLO * 2 + so, b_lo + gb);
    }
}

__device__ __forceinline__ void gemm_tile_mma(
    const __half* __restrict__ a, size_t arow0,
    const __half* __restrict__ b_hi, const __half* __restrict__ b_lo, size_t brow0,
    float acc[4][4][4])
{
    extern __shared__ __half sm[];
    const int tid = threadIdx.x;
    const int wid = tid >> 5, lane = tid & 31;
    const int mg = (wid & 3) * 64;
    const int ng = (wid >> 2) * 32;

    #pragma unroll
    for (int m = 0; m < 4; m++)
        #pragma unroll
        for (int n = 0; n < 4; n++)
            #pragma unroll
            for (int v = 0; v < 4; v++) acc[m][n][v] = 0.f;

    const uint32_t sb = smem_u32(sm);
    const int a_row_l = (lane & 15);
    const int a_col_l = ((lane >> 4) << 3);
    const int b_row_l = ((lane >> 4) << 3) + (lane & 7);
    const int b_col_l = (((lane >> 3) & 1) << 3);

    g_prefetch(sb, 0, a, arow0, b_hi, b_lo, brow0, 0, tid);
    CP_COMMIT();

    for (int s = 0; s < 16; s++) {
        const int buf = s & 1;
        CP_WAIT(0);                 // stage s prefetch complete
        __syncthreads();            // all warps done with stage s-1 -> buf^1 reusable
        if (s + 1 < 16) {
            g_prefetch(sb, buf ^ 1, a, arow0, b_hi, b_lo, brow0, (s + 1) * 64, tid);
            CP_COMMIT();
        }

        const uint32_t st = sb + (uint32_t)buf * G_STAGE * 2;
        #pragma unroll
        for (int ks = 0; ks < 4; ks++) {
            uint32_t ar[4][4];
            #pragma unroll
            for (int m = 0; m < 4; m++) {
                uint32_t off = (uint32_t)((mg + m * 16 + a_row_l) * PA + ks * 16 + a_col_l) * 2;
                LDSM_X4(ar[m][0], ar[m][1], ar[m][2], ar[m][3], st + G_A * 2 + off);
            }
            #pragma unroll
            for (int p = 0; p < 2; p++) {
                uint32_t off = (uint32_t)((ng + p * 16 + b_row_l) * PA + ks * 16 + b_col_l) * 2;
                uint32_t bh4[4], bl4[4];
                LDSM_X4(bh4[0], bh4[1], bh4[2], bh4[3], st + G_BHI * 2 + off);
                LDSM_X4(bl4[0], bl4[1], bl4[2], bl4[3], st + G_BLO * 2 + off);
                #pragma unroll
                for (int m = 0; m < 4; m++) {
                    mma_fp16(acc[m][2*p],   ar[m], bh4);
                    mma_fp16(acc[m][2*p],   ar[m], bl4);
                    mma_fp16(acc[m][2*p+1], ar[m], bh4 + 2);
                    mma_fp16(acc[m][2*p+1], ar[m], bl4 + 2);
                }
            }
        }
        // no trailing sync: next iteration's top sync covers the WAR hazard
    }
}

// ---------------------------------------------------------------------------
// QKV GEMM: grid (32 mtiles of 256, 24 ntiles of 128).
// ---------------------------------------------------------------------------
__global__ __launch_bounds__(512) void gemm_qkv_tc(
    const float* __restrict__ bq, const float* __restrict__ bk, const float* __restrict__ bv)
{
    const int mt = blockIdx.x, nt = blockIdx.y;
    const size_t arow0 = (size_t)mt * 256;
    const size_t brow0 = (size_t)nt * 128;

    float acc[4][4][4];
    gemm_tile_mma(gx, arow0, gw_hi, gw_lo, brow0, acc);

    const int tid = threadIdx.x, wid = tid >> 5, lane = tid & 31;
    const int mg = (wid & 3) * 64;
    const int gcol0 = nt * 128 + (wid >> 2) * 32;
    const int which = gcol0 >> 10;
    const int h = (gcol0 & 1023) >> 6;
    const float* bias = (which == 0) ? bq : (which == 1) ? bk : bv;

    #pragma unroll
    for (int m = 0; m < 4; m++) {
        #pragma unroll
        for (int n4 = 0; n4 < 4; n4++) {
            #pragma unroll
            for (int half_ = 0; half_ < 2; half_++) {
                int r = mg + m * 16 + (lane >> 2) + half_ * 8;
                int e = (gcol0 & 63) + n4 * 8 + (lane & 3) * 2;
                size_t mrow = arow0 + r;
                int b = (int)(mrow / S), sidx = (int)(mrow % S);
                int bhidx = b * H + h;
                float v0 = acc[m][n4][half_ * 2 + 0] + bias[h * DH + e];
                float v1 = acc[m][n4][half_ * 2 + 1] + bias[h * DH + e + 1];
                if (which == 0) {
                    v0 *= SCALE; v1 *= SCALE;
                    size_t base = ((size_t)bhidx * S + sidx) * DH + e;
                    *(__half2*)&gq[base] = __floats2half2_rn(v0, v1);
                } else if (which == 1) {
                    __half h0, l0, h1, l1;
                    split2h(v0, h0, l0); split2h(v1, h1, l1);
                    size_t base = ((size_t)bhidx * S + sidx) * DH + e;
                    __half2 th; th.x = h0; th.y = h1;
                    __half2 tl; tl.x = l0; tl.y = l1;
                    *(__half2*)&gk_hi[base] = th;
                    *(__half2*)&gk_lo[base] = tl;
                } else {
                    __half h0, l0, h1, l1;
                    split2h(v0, h0, l0); split2h(v1, h1, l1);
                    size_t base = ((size_t)bhidx * DH + e) * S + sidx;
                    gvt_hi[base] = h0;     gvt_lo[base] = l0;
                    gvt_hi[base + S] = h1; gvt_lo[base + S] = l1;
                }
            }
        }
    }
}

// ---------------------------------------------------------------------------
// Output GEMM: grid (32 mtiles of 256, 8 ntiles of 128).
// ---------------------------------------------------------------------------
__global__ __launch_bounds__(512) void gemm_out_tc(const float* __restrict__ bo,
                                                   float* __restrict__ out)
{
    const int mt = blockIdx.x, nt = blockIdx.y;
    const size_t arow0 = (size_t)mt * 256;

    float acc[4][4][4];
    gemm_tile_mma(gh, arow0, gwo_hi, gwo_lo, (size_t)nt * 128, acc);

    const int tid = threadIdx.x, wid = tid >> 5, lane = tid & 31;
    const int mg = (wid & 3) * 64;
    const int gcol0 = nt * 128 + (wid >> 2) * 32;

    #pragma unroll
    for (int m = 0; m < 4; m++) {
        #pragma unroll
        for (int n4 = 0; n4 < 4; n4++) {
            #pragma unroll
            for (int half_ = 0; half_ < 2; half_++) {
                int r = mg + m * 16 + (lane >> 2) + half_ * 8;
                int c = gcol0 + n4 * 8 + (lane & 3) * 2;
                size_t mrow = arow0 + r;
                float2 w = {acc[m][n4][half_ * 2 + 0] + bo[c],
                            acc[m][n4][half_ * 2 + 1] + bo[c + 1]};
                *(float2*)&out[mrow * DM + c] = w;
            }
        }
    }
}

// ---------------------------------------------------------------------------
// Attention (FA2, fp16 2-term), double-buffered KV, single sync per kt-tile.
// ---------------------------------------------------------------------------
#define A_Q 0
#define A_KV0 (128 * PA)
#define A_KV_COMP (64 * PA)
#define A_KV_STAGE (4 * A_KV_COMP)
#define ATT_BYTES ((128 * PA + 2 * A_KV_STAGE) * 2)   // 92160 B

__device__ __forceinline__ void a_prefetch_kv(uint32_t sb, int buf, int bh, int kt, int tid)
{
    uint32_t st = sb + (uint32_t)(A_KV0 + buf * A_KV_STAGE) * 2;
    #pragma unroll
    for (int it = 0; it < 2; it++) {
        int c = it * 256 + tid;
        int row = c >> 3, c8 = c & 7;
        uint32_t so = (uint32_t)(row * PA + c8 * 8) * 2;
        size_t gk = ((size_t)bh * S + kt * 64 + row) * DH + c8 * 8;
        size_t gv = ((size_t)bh * DH + row) * S + kt * 64 + c8 * 8;
        CP_ASYNC16(st + 0 * A_KV_COMP * 2 + so, gk_hi + gk);
        CP_ASYNC16(st + 1 * A_KV_COMP * 2 + so, gk_lo + gk);
        CP_ASYNC16(st + 2 * A_KV_COMP * 2 + so, gvt_hi + gv);
        CP_ASYNC16(st + 3 * A_KV_COMP * 2 + so, gvt_lo + gv);
    }
}

__global__ __launch_bounds__(256) void attn_mma()
{
    extern __shared__ __half sm[];
    const int qt = blockIdx.x;
    const int bh = blockIdx.y;
    const int tid = threadIdx.x, wid = tid >> 5, lane = tid & 31;
    const int base_m = wid * 16;
    const uint32_t sb = smem_u32(sm);
    const int a_row_l = (lane & 15);
    const int a_col_l = ((lane >> 4) << 3);
    const int b_row_l = ((lane >> 4) << 3) + (lane & 7);
    const int b_col_l = (((lane >> 3) & 1) << 3);

    a_prefetch_kv(sb, 0, bh, 0, tid);
    CP_COMMIT();

    const size_t qbase = ((size_t)bh * S + qt * 128) * DH;
    #pragma unroll
    for (int it = 0; it < 4; it++) {
        int c = it * 256 + tid;
        int row = c >> 3, c8 = c & 7;
        *(uint4*)&sm[A_Q + row * PA + c8 * 8] = *(const uint4*)(gq + qbase + (size_t)row * DH + c8 * 8);
    }

    float o[8][4];
    #pragma unroll
    for (int n = 0; n < 8; n++)
        #pragma unroll
        for (int v = 0; v < 4; v++) o[n][v] = 0.f;
    float mrow[2] = {-INFINITY, -INFINITY};
    float lrow[2] = {0.f, 0.f};

    for (int kt = 0; kt < S / 64; kt++) {
        const int buf = kt & 1;
        CP_WAIT(0);
        __syncthreads();
        if (kt + 1 < S / 64) {
            a_prefetch_kv(sb, buf ^ 1, bh, kt + 1, tid);
            CP_COMMIT();
        }

        const uint32_t st = sb + (uint32_t)(A_KV0 + buf * A_KV_STAGE) * 2;

        float sc[8][4];
        #pragma unroll
        for (int n = 0; n < 8; n++)
            #pragma unroll
            for (int v = 0; v < 4; v++) sc[n][v] = 0.f;

        #pragma unroll
        for (int ks = 0; ks < 4; ks++) {
            uint32_t ar[4];
            uint32_t aoff = (uint32_t)((base_m + a_row_l) * PA + ks * 16 + a_col_l) * 2;
            LDSM_X4(ar[0], ar[1], ar[2], ar[3], sb + A_Q * 2 + aoff);
            #pragma unroll
            for (int p = 0; p < 4; p++) {
                uint32_t boff = (uint32_t)((p * 16 + b_row_l) * PA + ks * 16 + b_col_l) * 2;
                uint32_t kh4[4], kl4[4];
                LDSM_X4(kh4[0], kh4[1], kh4[2], kh4[3], st + 0 * A_KV_COMP * 2 + boff);
                LDSM_X4(kl4[0], kl4[1], kl4[2], kl4[3], st + 1 * A_KV_COMP * 2 + boff);
                mma_fp16(sc[2*p],   ar, kh4);
                mma_fp16(sc[2*p],   ar, kl4);
                mma_fp16(sc[2*p+1], ar, kh4 + 2);
                mma_fp16(sc[2*p+1], ar, kl4 + 2);
            }
        }

        #pragma unroll
        for (int half_ = 0; half_ < 2; half_++) {
            const int ci = half_ * 2;
            float mx = -INFINITY;
            #pragma unroll
            for (int n = 0; n < 8; n++)
                mx = fmaxf(mx, fmaxf(sc[n][ci], sc[n][ci + 1]));
            mx = fmaxf(mx, __shfl_xor_sync(0xffffffffu, mx, 1));
            mx = fmaxf(mx, __shfl_xor_sync(0xffffffffu, mx, 2));
            float mnew = fmaxf(mrow[half_], mx);
            float f = __expf(mrow[half_] - mnew);
            mrow[half_] = mnew;
            float rs = 0.f;
            #pragma unroll
            for (int n = 0; n < 8; n++) {
                sc[n][ci]     = __expf(sc[n][ci]     - mnew);
                sc[n][ci + 1] = __expf(sc[n][ci + 1] - mnew);
                rs += sc[n][ci] + sc[n][ci + 1];
            }
            rs += __shfl_xor_sync(0xffffffffu, rs, 1);
            rs += __shfl_xor_sync(0xffffffffu, rs, 2);
            lrow[half_] = lrow[half_] * f + rs;
            #pragma unroll
            for (int n = 0; n < 8; n++) {
                o[n][ci] *= f;
                o[n][ci + 1] *= f;
            }
        }

        uint32_t pa[4][4];
        #pragma unroll
        for (int ks = 0; ks < 4; ks++) {
            #pragma unroll
            for (int q = 0; q < 4; q++) {
                int n = 2 * ks + (q >> 1);
                int pr = (q & 1) * 2;
                __half2 t = __floats2half2_rn(sc[n][pr], sc[n][pr + 1]);
                pa[ks][q] = *(uint32_t*)&t;
            }
        }

        #pragma unroll
        for (int ks = 0; ks < 4; ks++) {
            #pragma unroll
            for (int p = 0; p < 4; p++) {
                uint32_t boff = (uint32_t)((p * 16 + b_row_l) * PA + ks * 16 + b_col_l) * 2;
                uint32_t vh4[4], vl4[4];
                LDSM_X4(vh4[0], vh4[1], vh4[2], vh4[3], st + 2 * A_KV_COMP * 2 + boff);
                LDSM_X4(vl4[0], vl4[1], vl4[2], vl4[3], st + 3 * A_KV_COMP * 2 + boff);
                mma_fp16(o[2*p],   pa[ks], vh4);
                mma_fp16(o[2*p],   pa[ks], vl4);
                mma_fp16(o[2*p+1], pa[ks], vh4 + 2);
                mma_fp16(o[2*p+1], pa[ks], vl4 + 2);
            }
        }
    }

    const float inv0 = 1.f / lrow[0];
    const float inv1 = 1.f / lrow[1];
    const int b = bh >> 4, h = bh & 15;
    const int s0 = qt * 128 + base_m + (lane >> 2);
    const size_t tok0 = (size_t)b * S + s0;
    const size_t tok1 = tok0 + 8;
    #pragma unroll
    for (int n = 0; n < 8; n++) {
        int col = h * DH + n * 8 + (lane & 3) * 2;
        *(__half2*)&gh[tok0 * DM + col] = __floats2half2_rn(o[n][0] * inv0, o[n][1] * inv0);
        *(__half2*)&gh[tok1 * DM + col] = __floats2half2_rn(o[n][2] * inv1, o[n][3] * inv1);
    }
}

// ---------------------------------------------------------------------------
extern "C" void kernel_launch(void* const* d_in, const int* in_sizes, int n_in,
                              void* d_out, int out_size)
{
    const float* x  = (const float*)d_in[0];
    const float* Wq = (const float*)d_in[1];
    const float* bq = (const float*)d_in[2];
    const float* Wk = (const float*)d_in[3];
    const float* bk = (const float*)d_in[4];
    const float* Wv = (const float*)d_in[5];
    const float* bv = (const float*)d_in[6];
    const float* Wo = (const float*)d_in[7];
    const float* bo = (const float*)d_in[8];
    float* out = (float*)d_out;

    static bool init = false;
    if (!init) {
        cudaFuncSetAttribute(gemm_qkv_tc, cudaFuncAttributeMaxDynamicSharedMemorySize, GSM_BYTES);
        cudaFuncSetAttribute(gemm_out_tc, cudaFuncAttributeMaxDynamicSharedMemorySize, GSM_BYTES);
        cudaFuncSetAttribute(attn_mma,    cudaFuncAttributeMaxDynamicSharedMemorySize, ATT_BYTES);
        init = true;
    }

    // 1. fused prep
    prep_kernel<<<6144, 256>>>(x, Wq, Wk, Wv, Wo);

    // 2. QKV projection (fp16 2-term HMMA, 2-stage single-sync pipeline)
    gemm_qkv_tc<<<dim3(32, 24), 512, GSM_BYTES>>>(bq, bk, bv);

    // 3. attention (fp16 2-term HMMA, single-sync pipeline)
    attn_mma<<<dim3(16, 64), 256, ATT_BYTES>>>();

    // 4. output projection
    gemm_out_tc<<<dim3(32, 8), 512, GSM_BYTES>>>(bo, out);
}

// round 12
// speedup vs baseline: 1.6093x; 1.0139x over previous
#include <cuda_runtime.h>
#include <cuda_fp16.h>
#include <math.h>
#include <cstdint>

#define B 4
#define H 16
#define S 2048
#define DM 1024
#define DH 64
#define QSCALE 0.18033688f   // (1/8) * log2(e) : scores in log2 domain
#define NTOK (B*S)   // 8192

// ---------------------------------------------------------------------------
// Scratch (device globals: no allocations allowed)
// ---------------------------------------------------------------------------
__device__ __half gx[(size_t)NTOK*DM];
__device__ __half gw_hi[(size_t)3*H*DH*DM], gw_lo[(size_t)3*H*DH*DM];
__device__ __half gwo_hi[(size_t)DM*DM], gwo_lo[(size_t)DM*DM];
__device__ __half gh[(size_t)NTOK*DM];

__device__ __half gq[(size_t)B*H*S*DH];
__device__ __half gk_hi[(size_t)B*H*S*DH], gk_lo[(size_t)B*H*S*DH];
__device__ __half gvt_hi[(size_t)B*H*DH*S], gvt_lo[(size_t)B*H*DH*S];

// ---------------------------------------------------------------------------
// PTX helpers
// ---------------------------------------------------------------------------
__device__ __forceinline__ uint32_t smem_u32(const void* p) {
    uint32_t a;
    asm("{ .reg .u64 t; cvta.to.shared.u64 t, %1; cvt.u32.u64 %0, t; }" : "=r"(a) : "l"(p));
    return a;
}

#define LDSM_X4(r0, r1, r2, r3, addr) \
    asm volatile("ldmatrix.sync.aligned.m8n8.x4.shared.b16 {%0,%1,%2,%3}, [%4];" \
                 : "=r"(r0), "=r"(r1), "=r"(r2), "=r"(r3) : "r"(addr))

__device__ __forceinline__ void mma_fp16(float* c, const uint32_t* a, const uint32_t* b) {
    asm volatile("mma.sync.aligned.m16n8k16.row.col.f32.f16.f16.f32 "
                 "{%0,%1,%2,%3}, {%4,%5,%6,%7}, {%8,%9}, {%0,%1,%2,%3};"
                 : "+f"(c[0]), "+f"(c[1]), "+f"(c[2]), "+f"(c[3])
                 : "r"(a[0]), "r"(a[1]), "r"(a[2]), "r"(a[3]), "r"(b[0]), "r"(b[1]));
}

#define CP_ASYNC16(dst_u32, src_ptr) \
    asm volatile("cp.async.ca.shared.global [%0], [%1], 16;" \
                 :: "r"(dst_u32), "l"(src_ptr) : "memory")
#define CP_COMMIT() asm volatile("cp.async.commit_group;" ::: "memory")
#define CP_WAIT(n)  asm volatile("cp.async.wait_group %0;" :: "n"(n) : "memory")

__device__ __forceinline__ float exp2f_fast(float x) {
    float y; asm("ex2.approx.f32 %0, %1;" : "=f"(y) : "f"(x)); return y;
}
__device__ __forceinline__ uint32_t h2exp2_fast(uint32_t x) {
    uint32_t y; asm("ex2.approx.f16x2 %0, %1;" : "=r"(y) : "r"(x)); return y;
}

__device__ __forceinline__ void split2h(float a, __half& h, __half& l) {
    h = __float2half_rn(a);
    l = __float2half_rn(a - __half2float(h));
}

// ---------------------------------------------------------------------------
// Fused prep (validated R8)
// ---------------------------------------------------------------------------
__global__ __launch_bounds__(256) void prep_kernel(
    const float* __restrict__ x,
    const float* __restrict__ Wq, const float* __restrict__ Wk, const float* __restrict__ Wv,
    const float* __restrict__ Wo)
{
    const int bid = blockIdx.x;
    const int tid = threadIdx.x;

    if (bid < 2048) {
        __half2* dp = (__half2*)gx;
        #pragma unroll
        for (int j = 0; j < 4; j++) {
            int i = bid * 1024 + j * 256 + tid;
            float4 v = ((const float4*)x)[i];
            dp[2*i]   = __floats2half2_rn(v.x, v.y);
            dp[2*i+1] = __floats2half2_rn(v.z, v.w);
        }
        return;
    }

    __shared__ float tile[32][33];
    const int t = bid - 2048;
    const float* src;
    __half *dst_hi, *dst_lo;
    int d0, e0, in_stride, out_stride;
    size_t in_base, out_base;

    if (t < 3072) {
        const int which = t >> 10;
        const int r = t & 1023;
        const int h = r >> 6;
        const int tl = r & 63;
        const int tk = tl >> 1, te = tl & 1;
        src = (which == 0) ? Wq : (which == 1) ? Wk : Wv;
        d0 = tk * 32; e0 = te * 32;
        in_stride = DH; out_stride = DM;
        in_base  = (size_t)h * DM * DH;
        out_base = ((size_t)(which * H + h) * DH) * DM;
        dst_hi = gw_hi; dst_lo = gw_lo;
    } else {
        const int t2 = t - 3072;
        d0 = (t2 >> 5) * 32; e0 = (t2 & 31) * 32;
        src = Wo; in_stride = DM; out_stride = DM;
        in_base = 0; out_base = 0;
        dst_hi = gwo_hi; dst_lo = gwo_lo;
    }

    const int tx = tid & 31, ty = tid >> 5;
    #pragma unroll
    for (int p = 0; p < 4; p++) {
        int row = ty + p * 8;
        tile[row][tx] = src[in_base + (size_t)(d0 + row) * in_stride + e0 + tx];
    }
    __syncthreads();
    #pragma unroll
    for (int p = 0; p < 4; p++) {
        int erow = ty + p * 8;
        float v = tile[tx][erow];
        __half h, l; split2h(v, h, l);
        size_t oi = out_base + (size_t)(e0 + erow) * out_stride + d0 + tx;
        dst_hi[oi] = h; dst_lo[oi] = l;
    }
}

// ---------------------------------------------------------------------------
// GEMM core (R11: 2-stage, single sync per stage)
// ---------------------------------------------------------------------------
#define PA 72
#define G_A 0
#define G_BHI (256 * PA)
#define G_BLO (256 * PA + 128 * PA)
#define G_STAGE (512 * PA)
#define GSM_BYTES (2 * G_STAGE * 2)       // 147456 B

__device__ __forceinline__ void g_prefetch(
    uint32_t sb, int buf,
    const __half* a, size_t arow0,
    const __half* b_hi, const __half* b_lo, size_t brow0,
    int k0, int tid)
{
    uint32_t st = sb + (uint32_t)buf * G_STAGE * 2;
    #pragma unroll
    for (int it = 0; it < 4; it++) {
        int c = it * 512 + tid;
        int row = c >> 3, c8 = c & 7;
        uint32_t so = (uint32_t)(row * PA + c8 * 8) * 2;
        CP_ASYNC16(st + G_A * 2 + so, a + (arow0 + row) * (size_t)DM + k0 + c8 * 8);
    }
    #pragma unroll
    for (int it = 0; it < 2; it++) {
        int c = it * 512 + tid;
        int row = c >> 3, c8 = c & 7;
        uint32_t so = (uint32_t)(row * PA + c8 * 8) * 2;
        size_t gb = (brow0 + row) * (size_t)DM + k0 + c8 * 8;
        CP_ASYNC16(st + G_BHI * 2 + so, b_hi + gb);
        CP_ASYNC16(st + G_BLO * 2 + so, b_lo + gb);
    }
}

__device__ __forceinline__ void gemm_tile_mma(
    const __half* __restrict__ a, size_t arow0,
    const __half* __restrict__ b_hi, const __half* __restrict__ b_lo, size_t brow0,
    float acc[4][4][4])
{
    extern __shared__ __half sm[];
    const int tid = threadIdx.x;
    const int wid = tid >> 5, lane = tid & 31;
    const int mg = (wid & 3) * 64;
    const int ng = (wid >> 2) * 32;

    #pragma unroll
    for (int m = 0; m < 4; m++)
        #pragma unroll
        for (int n = 0; n < 4; n++)
            #pragma unroll
            for (int v = 0; v < 4; v++) acc[m][n][v] = 0.f;

    const uint32_t sb = smem_u32(sm);
    const int a_row_l = (lane & 15);
    const int a_col_l = ((lane >> 4) << 3);
    const int b_row_l = ((lane >> 4) << 3) + (lane & 7);
    const int b_col_l = (((lane >> 3) & 1) << 3);

    g_prefetch(sb, 0, a, arow0, b_hi, b_lo, brow0, 0, tid);
    CP_COMMIT();

    for (int s = 0; s < 16; s++) {
        const int buf = s & 1;
        CP_WAIT(0);
        __syncthreads();
        if (s + 1 < 16) {
            g_prefetch(sb, buf ^ 1, a, arow0, b_hi, b_lo, brow0, (s + 1) * 64, tid);
            CP_COMMIT();
        }

        const uint32_t st = sb + (uint32_t)buf * G_STAGE * 2;
        #pragma unroll
        for (int ks = 0; ks < 4; ks++) {
            uint32_t ar[4][4];
            #pragma unroll
            for (int m = 0; m < 4; m++) {
                uint32_t off = (uint32_t)((mg + m * 16 + a_row_l) * PA + ks * 16 + a_col_l) * 2;
                LDSM_X4(ar[m][0], ar[m][1], ar[m][2], ar[m][3], st + G_A * 2 + off);
            }
            #pragma unroll
            for (int p = 0; p < 2; p++) {
                uint32_t off = (uint32_t)((ng + p * 16 + b_row_l) * PA + ks * 16 + b_col_l) * 2;
                uint32_t bh4[4], bl4[4];
                LDSM_X4(bh4[0], bh4[1], bh4[2], bh4[3], st + G_BHI * 2 + off);
                LDSM_X4(bl4[0], bl4[1], bl4[2], bl4[3], st + G_BLO * 2 + off);
                #pragma unroll
                for (int m = 0; m < 4; m++) {
                    mma_fp16(acc[m][2*p],   ar[m], bh4);
                    mma_fp16(acc[m][2*p],   ar[m], bl4);
                    mma_fp16(acc[m][2*p+1], ar[m], bh4 + 2);
                    mma_fp16(acc[m][2*p+1], ar[m], bl4 + 2);
                }
            }
        }
    }
}

// ---------------------------------------------------------------------------
// QKV GEMM: grid (32 mtiles of 256, 24 ntiles of 128).
// Q pre-scaled by (1/8)*log2(e)  -> attention scores in log2 domain.
// ---------------------------------------------------------------------------
__global__ __launch_bounds__(512) void gemm_qkv_tc(
    const float* __restrict__ bq, const float* __restrict__ bk, const float* __restrict__ bv)
{
    const int mt = blockIdx.x, nt = blockIdx.y;
    const size_t arow0 = (size_t)mt * 256;
    const size_t brow0 = (size_t)nt * 128;

    float acc[4][4][4];
    gemm_tile_mma(gx, arow0, gw_hi, gw_lo, brow0, acc);

    const int tid = threadIdx.x, wid = tid >> 5, lane = tid & 31;
    const int mg = (wid & 3) * 64;
    const int gcol0 = nt * 128 + (wid >> 2) * 32;
    const int which = gcol0 >> 10;
    const int h = (gcol0 & 1023) >> 6;
    const float* bias = (which == 0) ? bq : (which == 1) ? bk : bv;

    #pragma unroll
    for (int m = 0; m < 4; m++) {
        #pragma unroll
        for (int n4 = 0; n4 < 4; n4++) {
            #pragma unroll
            for (int half_ = 0; half_ < 2; half_++) {
                int r = mg + m * 16 + (lane >> 2) + half_ * 8;
                int e = (gcol0 & 63) + n4 * 8 + (lane & 3) * 2;
                size_t mrow = arow0 + r;
                int b = (int)(mrow / S), sidx = (int)(mrow % S);
                int bhidx = b * H + h;
                float v0 = acc[m][n4][half_ * 2 + 0] + bias[h * DH + e];
                float v1 = acc[m][n4][half_ * 2 + 1] + bias[h * DH + e + 1];
                if (which == 0) {
                    v0 *= QSCALE; v1 *= QSCALE;
                    size_t base = ((size_t)bhidx * S + sidx) * DH + e;
                    *(__half2*)&gq[base] = __floats2half2_rn(v0, v1);
                } else if (which == 1) {
                    __half h0, l0, h1, l1;
                    split2h(v0, h0, l0); split2h(v1, h1, l1);
                    size_t base = ((size_t)bhidx * S + sidx) * DH + e;
                    __half2 th; th.x = h0; th.y = h1;
                    __half2 tl; tl.x = l0; tl.y = l1;
                    *(__half2*)&gk_hi[base] = th;
                    *(__half2*)&gk_lo[base] = tl;
                } else {
                    __half h0, l0, h1, l1;
                    split2h(v0, h0, l0); split2h(v1, h1, l1);
                    size_t base = ((size_t)bhidx * DH + e) * S + sidx;
                    gvt_hi[base] = h0;     gvt_lo[base] = l0;
                    gvt_hi[base + S] = h1; gvt_lo[base + S] = l1;
                }
            }
        }
    }
}

// ---------------------------------------------------------------------------
// Output GEMM: grid (32 mtiles of 256, 8 ntiles of 128).
// ---------------------------------------------------------------------------
__global__ __launch_bounds__(512) void gemm_out_tc(const float* __restrict__ bo,
                                                   float* __restrict__ out)
{
    const int mt = blockIdx.x, nt = blockIdx.y;
    const size_t arow0 = (size_t)mt * 256;

    float acc[4][4][4];
    gemm_tile_mma(gh, arow0, gwo_hi, gwo_lo, (size_t)nt * 128, acc);

    const int tid = threadIdx.x, wid = tid >> 5, lane = tid & 31;
    const int mg = (wid & 3) * 64;
    const int gcol0 = nt * 128 + (wid >> 2) * 32;

    #pragma unroll
    for (int m = 0; m < 4; m++) {
        #pragma unroll
        for (int n4 = 0; n4 < 4; n4++) {
            #pragma unroll
            for (int half_ = 0; half_ < 2; half_++) {
                int r = mg + m * 16 + (lane >> 2) + half_ * 8;
                int c = gcol0 + n4 * 8 + (lane & 3) * 2;
                size_t mrow = arow0 + r;
                float2 w = {acc[m][n4][half_ * 2 + 0] + bo[c],
                            acc[m][n4][half_ * 2 + 1] + bo[c + 1]};
                *(float2*)&out[mrow * DM + c] = w;
            }
        }
    }
}

// ---------------------------------------------------------------------------
// Attention (FA2, fp16 2-term), log2-domain softmax with f16x2 EX2.
// ---------------------------------------------------------------------------
#define A_Q 0
#define A_KV0 (128 * PA)
#define A_KV_COMP (64 * PA)
#define A_KV_STAGE (4 * A_KV_COMP)
#define ATT_BYTES ((128 * PA + 2 * A_KV_STAGE) * 2)   // 92160 B

__device__ __forceinline__ void a_prefetch_kv(uint32_t sb, int buf, int bh, int kt, int tid)
{
    uint32_t st = sb + (uint32_t)(A_KV0 + buf * A_KV_STAGE) * 2;
    #pragma unroll
    for (int it = 0; it < 2; it++) {
        int c = it * 256 + tid;
        int row = c >> 3, c8 = c & 7;
        uint32_t so = (uint32_t)(row * PA + c8 * 8) * 2;
        size_t gk = ((size_t)bh * S + kt * 64 + row) * DH + c8 * 8;
        size_t gv = ((size_t)bh * DH + row) * S + kt * 64 + c8 * 8;
        CP_ASYNC16(st + 0 * A_KV_COMP * 2 + so, gk_hi + gk);
        CP_ASYNC16(st + 1 * A_KV_COMP * 2 + so, gk_lo + gk);
        CP_ASYNC16(st + 2 * A_KV_COMP * 2 + so, gvt_hi + gv);
        CP_ASYNC16(st + 3 * A_KV_COMP * 2 + so, gvt_lo + gv);
    }
}

__global__ __launch_bounds__(256) void attn_mma()
{
    extern __shared__ __half sm[];
    const int qt = blockIdx.x;
    const int bh = blockIdx.y;
    const int tid = threadIdx.x, wid = tid >> 5, lane = tid & 31;
    const int base_m = wid * 16;
    const uint32_t sb = smem_u32(sm);
    const int a_row_l = (lane & 15);
    const int a_col_l = ((lane >> 4) << 3);
    const int b_row_l = ((lane >> 4) << 3) + (lane & 7);
    const int b_col_l = (((lane >> 3) & 1) << 3);

    a_prefetch_kv(sb, 0, bh, 0, tid);
    CP_COMMIT();

    const size_t qbase = ((size_t)bh * S + qt * 128) * DH;
    #pragma unroll
    for (int it = 0; it < 4; it++) {
        int c = it * 256 + tid;
        int row = c >> 3, c8 = c & 7;
        *(uint4*)&sm[A_Q + row * PA + c8 * 8] = *(const uint4*)(gq + qbase + (size_t)row * DH + c8 * 8);
    }

    float o[8][4];
    #pragma unroll
    for (int n = 0; n < 8; n++)
        #pragma unroll
        for (int v = 0; v < 4; v++) o[n][v] = 0.f;
    float mrow[2] = {-INFINITY, -INFINITY};
    float lrow[2] = {0.f, 0.f};

    for (int kt = 0; kt < S / 64; kt++) {
        const int buf = kt & 1;
        CP_WAIT(0);
        __syncthreads();
        if (kt + 1 < S / 64) {
            a_prefetch_kv(sb, buf ^ 1, bh, kt + 1, tid);
            CP_COMMIT();
        }

        const uint32_t st = sb + (uint32_t)(A_KV0 + buf * A_KV_STAGE) * 2;

        // ---- S(log2 domain) = Q K^T (2-term) ----
        float sc[8][4];
        #pragma unroll
        for (int n = 0; n < 8; n++)
            #pragma unroll
            for (int v = 0; v < 4; v++) sc[n][v] = 0.f;

        #pragma unroll
        for (int ks = 0; ks < 4; ks++) {
            uint32_t ar[4];
            uint32_t aoff = (uint32_t)((base_m + a_row_l) * PA + ks * 16 + a_col_l) * 2;
            LDSM_X4(ar[0], ar[1], ar[2], ar[3], sb + A_Q * 2 + aoff);
            #pragma unroll
            for (int p = 0; p < 4; p++) {
                uint32_t boff = (uint32_t)((p * 16 + b_row_l) * PA + ks * 16 + b_col_l) * 2;
                uint32_t kh4[4], kl4[4];
                LDSM_X4(kh4[0], kh4[1], kh4[2], kh4[3], st + 0 * A_KV_COMP * 2 + boff);
                LDSM_X4(kl4[0], kl4[1], kl4[2], kl4[3], st + 1 * A_KV_COMP * 2 + boff);
                mma_fp16(sc[2*p],   ar, kh4);
                mma_fp16(sc[2*p],   ar, kl4);
                mma_fp16(sc[2*p+1], ar, kh4 + 2);
                mma_fp16(sc[2*p+1], ar, kl4 + 2);
            }
        }

        // ---- streaming softmax in log2 domain; P via ex2.f16x2 ----
        uint32_t ph2[8][2];
        #pragma unroll
        for (int half_ = 0; half_ < 2; half_++) {
            const int ci = half_ * 2;
            float mx = -INFINITY;
            #pragma unroll
            for (int n = 0; n < 8; n++)
                mx = fmaxf(mx, fmaxf(sc[n][ci], sc[n][ci + 1]));
            mx = fmaxf(mx, __shfl_xor_sync(0xffffffffu, mx, 1));
            mx = fmaxf(mx, __shfl_xor_sync(0xffffffffu, mx, 2));
            float mnew = fmaxf(mrow[half_], mx);
            float f = exp2f_fast(mrow[half_] - mnew);
            mrow[half_] = mnew;
            float rs = 0.f;
            #pragma unroll
            for (int n = 0; n < 8; n++) {
                __half2 hx = __floats2half2_rn(sc[n][ci] - mnew, sc[n][ci + 1] - mnew);
                uint32_t hp = h2exp2_fast(*(uint32_t*)&hx);
                ph2[n][half_] = hp;
                float2 tf = __half22float2(*(__half2*)&hp);
                rs += tf.x + tf.y;
            }
            rs += __shfl_xor_sync(0xffffffffu, rs, 1);
            rs += __shfl_xor_sync(0xffffffffu, rs, 2);
            lrow[half_] = lrow[half_] * f + rs;
            #pragma unroll
            for (int n = 0; n < 8; n++) {
                o[n][ci] *= f;
                o[n][ci + 1] *= f;
            }
        }

        // ---- O += P V (2-term), P fragments = ph2 directly ----
        #pragma unroll
        for (int ks = 0; ks < 4; ks++) {
            uint32_t pa[4];
            #pragma unroll
            for (int q = 0; q < 4; q++)
                pa[q] = ph2[2 * ks + (q >> 1)][q & 1];
            #pragma unroll
            for (int p = 0; p < 4; p++) {
                uint32_t boff = (uint32_t)((p * 16 + b_row_l) * PA + ks * 16 + b_col_l) * 2;
                uint32_t vh4[4], vl4[4];
                LDSM_X4(vh4[0], vh4[1], vh4[2], vh4[3], st + 2 * A_KV_COMP * 2 + boff);
                LDSM_X4(vl4[0], vl4[1], vl4[2], vl4[3], st + 3 * A_KV_COMP * 2 + boff);
                mma_fp16(o[2*p],   pa, vh4);
                mma_fp16(o[2*p],   pa, vl4);
                mma_fp16(o[2*p+1], pa, vh4 + 2);
                mma_fp16(o[2*p+1], pa, vl4 + 2);
            }
        }
    }

    const float inv0 = 1.f / lrow[0];
    const float inv1 = 1.f / lrow[1];
    const int b = bh >> 4, h = bh & 15;
    const int s0 = qt * 128 + base_m + (lane >> 2);
    const size_t tok0 = (size_t)b * S + s0;
    const size_t tok1 = tok0 + 8;
    #pragma unroll
    for (int n = 0; n < 8; n++) {
        int col = h * DH + n * 8 + (lane & 3) * 2;
        *(__half2*)&gh[tok0 * DM + col] = __floats2half2_rn(o[n][0] * inv0, o[n][1] * inv0);
        *(__half2*)&gh[tok1 * DM + col] = __floats2half2_rn(o[n][2] * inv1, o[n][3] * inv1);
    }
}

// ---------------------------------------------------------------------------
extern "C" void kernel_launch(void* const* d_in, const int* in_sizes, int n_in,
                              void* d_out, int out_size)
{
    const float* x  = (const float*)d_in[0];
    const float* Wq = (const float*)d_in[1];
    const float* bq = (const float*)d_in[2];
    const float* Wk = (const float*)d_in[3];
    const float* bk = (const float*)d_in[4];
    const float* Wv = (const float*)d_in[5];
    const float* bv = (const float*)d_in[6];
    const float* Wo = (const float*)d_in[7];
    const float* bo = (const float*)d_in[8];
    float* out = (float*)d_out;

    static bool init = false;
    if (!init) {
        cudaFuncSetAttribute(gemm_qkv_tc, cudaFuncAttributeMaxDynamicSharedMemorySize, GSM_BYTES);
        cudaFuncSetAttribute(gemm_out_tc, cudaFuncAttributeMaxDynamicSharedMemorySize, GSM_BYTES);
        cudaFuncSetAttribute(attn_mma,    cudaFuncAttributeMaxDynamicSharedMemorySize, ATT_BYTES);
        init = true;
    }

    // 1. fused prep
    prep_kernel<<<6144, 256>>>(x, Wq, Wk, Wv, Wo);

    // 2. QKV projection (Q pre-scaled into log2 domain)
    gemm_qkv_tc<<<dim3(32, 24), 512, GSM_BYTES>>>(bq, bk, bv);

    // 3. attention (f16x2 EX2 softmax)
    attn_mma<<<dim3(16, 64), 256, ATT_BYTES>>>();

    // 4. output projection
    gemm_out_tc<<<dim3(32, 8), 512, GSM_BYTES>>>(bo, out);
}